// round 2
// baseline (speedup 1.0000x reference)
#include <cuda_runtime.h>
#include <math.h>

// Per-(image,gt) max IoU (rounded quotient, exactly reference semantics),
// stored as float bits in uint (IoU >= 0 so uint max == float max).
__device__ unsigned int g_highest[1024];

__global__ void k_init_highest() {
    g_highest[threadIdx.x] = 0u;
}

// Deterministic IEEE round-to-nearest ops only (no FMA contraction, immune to
// fast_math) so that inter/union are bit-identical in both kernels.
__device__ __forceinline__ float box_area(const float4 b) {
    return __fmul_rn(__fsub_rn(b.z, b.x), __fsub_rn(b.w, b.y));
}

__device__ __forceinline__ void iou_iu(const float4 g, float areag,
                                       const float4 a, float areaa,
                                       float& inter, float& uni) {
    const float ix0 = fmaxf(g.x, a.x);
    const float iy0 = fmaxf(g.y, a.y);
    const float ix1 = fminf(g.z, a.z);
    const float iy1 = fminf(g.w, a.w);
    const float ww  = fmaxf(__fsub_rn(ix1, ix0), 0.0f);
    const float hh  = fmaxf(__fsub_rn(iy1, iy0), 0.0f);
    inter = __fmul_rn(ww, hh);
    uni   = __fsub_rn(__fadd_rn(areag, areaa), inter);
}

// ---------------------------------------------------------------------------
// Kernel 1: highest_per_gt[b][g] = max_a fl(inter/union) over rounded
// quotients. Block = 256 threads = 8 warps, blockIdx.y = image; each lane
// owns one gt; warps stride over an anchor chunk staged in SMEM (broadcast
// LDS.128). Division only when a candidate can beat the running max
// (band filter with 1e-6 margin -> cannot miss, few false positives).
// ---------------------------------------------------------------------------
#define K1_CHUNK 2048

__global__ __launch_bounds__(256) void k_gtmax(
    const float4* __restrict__ anchors,
    const float4* __restrict__ gt,
    int A)
{
    __shared__ float4 sanch[K1_CHUNK];
    const int b    = blockIdx.y;
    const int lane = threadIdx.x & 31;
    const int warp = threadIdx.x >> 5;

    const float4 g4   = gt[b * 32 + lane];
    const float areag = box_area(g4);

    const int base  = blockIdx.x * K1_CHUNK;
    const int count = min(K1_CHUNK, A - base);

    for (int i = threadIdx.x; i < count; i += 256)
        sanch[i] = anchors[base + i];
    __syncthreads();

    float vhat = 0.0f;
#pragma unroll 4
    for (int j = warp; j < count; j += 8) {
        const float4 a4   = sanch[j];                // warp-broadcast
        const float areaa = box_area(a4);
        float inter, uni;
        iou_iu(g4, areag, a4, areaa, inter, uni);
        if (inter > 0.0f &&
            inter >= __fmul_rn(__fmul_rn(vhat, uni), 0.999999f)) {
            const float q = __fdiv_rn(inter, uni);
            if (q > vhat) vhat = q;
        }
    }
    atomicMax(&g_highest[b * 32 + lane], __float_as_uint(vhat));
}

// ---------------------------------------------------------------------------
// Kernel 2: per (image, anchor) labeling + matched box + centerness.
// Rounded-quotient max with first-index argmax (reference semantics),
// low-quality equality check band-filtered per gt.
// ---------------------------------------------------------------------------
__global__ __launch_bounds__(256) void k_label(
    const float4* __restrict__ anchors,
    const float4* __restrict__ gt,
    float* __restrict__ out,
    int A, int B)
{
    __shared__ float4 sgt[32];    // gt box
    __shared__ float4 saux[32];   // {area_g, h, h*0.999999, unused}

    const int b = blockIdx.y;
    if (threadIdx.x < 32) {
        const float4 g4 = gt[b * 32 + threadIdx.x];
        sgt[threadIdx.x] = g4;
        const float h = __uint_as_float(g_highest[b * 32 + threadIdx.x]);
        saux[threadIdx.x] = make_float4(box_area(g4), h,
                                        __fmul_rn(h, 0.999999f), 0.0f);
    }
    __syncthreads();

    const int a = blockIdx.x * 256 + threadIdx.x;
    if (a >= A) return;

    const float4 a4   = anchors[a];
    const float areaa = box_area(a4);

    float vhat = 0.0f;   // running max of rounded quotients
    int   bidx = 0;      // first index achieving the max
    bool  lq   = false;

#pragma unroll 8
    for (int g = 0; g < 32; g++) {
        const float4 g4  = sgt[g];
        const float4 aux = saux[g];
        float inter, uni;
        iou_iu(g4, aux.x, a4, areaa, inter, uni);

        if (inter > 0.0f) {
            // band: candidate could exceed current max (no false negatives)
            const bool cmax = inter >= __fmul_rn(__fmul_rn(vhat, uni), 0.999999f);
            // band: candidate could equal this gt's global max
            const bool clq  = inter >= __fmul_rn(aux.z, uni);
            if (cmax || clq) {
                const float q = __fdiv_rn(inter, uni);
                if (cmax && q > vhat) { vhat = q; bidx = g; }
                if (q == aux.y) lq = true;
            }
        } else {
            // masked iou = 0; equals highest only if highest itself is 0
            if (aux.y == 0.0f) lq = true;
        }
    }

    const float val = vhat;
    const int gl = (lq || val >= 0.7f) ? 1 : ((val >= 0.3f) ? -1 : 0);
    const int ol = (lq || val >= 0.3f) ? 1 : ((val >= 0.1f) ? -1 : 0);

    const float4 tb4 = sgt[bidx];   // matched gt box (same argmax both matches)

    // deltas permuted [0,2,1,3]: [l=(cx-x0)/w, r=(x1-cx)/w, t=(cy-y0)/h, b=(y1-cy)/h]
    const float cx = 0.5f * (a4.x + a4.z);
    const float cy = 0.5f * (a4.y + a4.w);
    const float w  = a4.z - a4.x;
    const float hg = a4.w - a4.y;
    const float nl = cx - tb4.x;
    const float nr = tb4.z - cx;
    const float nt = cy - tb4.y;
    const float nb = tb4.w - cy;

    float cent = 0.0f;
    // sign(n/w) == sign(n) since w,h > 0, so in_box test on numerators is exact
    if (ol != 0 && nl >= 0.0f && nr >= 0.0f && nt >= 0.0f && nb >= 0.0f) {
        const float l  = __fdiv_rn(nl, w),  r  = __fdiv_rn(nr, w);
        const float t  = __fdiv_rn(nt, hg), bo = __fdiv_rn(nb, hg);
        const float minl = fminf(l, r),  maxl = fmaxf(l, r);
        const float mint = fminf(t, bo), maxt = fmaxf(t, bo);
        const float prod = __fmul_rn(__fdiv_rn(minl, __fadd_rn(maxl, 1e-12f)),
                                     __fdiv_rn(mint, __fadd_rn(maxt, 1e-12f)));
        cent = (prod > 0.0f) ? sqrtf(prod) : 0.0f;
    }

    // output layout: [gt_labels B*A][matched B*A*4][obj_labels B*A][centerness B*A]
    const size_t BA = (size_t)B * (size_t)A;
    const size_t o  = (size_t)b * (size_t)A + (size_t)a;

    out[o] = (float)gl;
    reinterpret_cast<float4*>(out + BA)[o] = tb4;
    out[BA * 5 + o] = (float)ol;
    out[BA * 6 + o] = cent;
}

extern "C" void kernel_launch(void* const* d_in, const int* in_sizes, int n_in,
                              void* d_out, int out_size)
{
    const float4* gt      = (const float4*)d_in[0];   // [B,32,4] f32
    const float4* anchors = (const float4*)d_in[1];   // [A,4]    f32
    const int B = in_sizes[0] / (32 * 4);
    const int A = in_sizes[1] / 4;
    float* out = (float*)d_out;

    k_init_highest<<<1, 1024>>>();

    dim3 g1((A + K1_CHUNK - 1) / K1_CHUNK, B);
    k_gtmax<<<g1, 256>>>(anchors, gt, A);

    dim3 g2((A + 255) / 256, B);
    k_label<<<g2, 256>>>(anchors, gt, out, A, B);
}

// round 3
// speedup vs baseline: 1.2296x; 1.2296x over previous
#include <cuda_runtime.h>
#include <math.h>

// Per-(image,gt) max IoU (rounded quotient, reference semantics via rounding
// monotonicity), stored as float bits in uint (IoU >= 0 so uint max == float max).
__device__ unsigned int g_highest[1024];

__global__ void k_init_highest() {
    g_highest[threadIdx.x] = 0u;
}

// Deterministic round-to-nearest ops (no FMA contraction, fast-math immune)
// so inter/union are bit-identical in both kernels.
__device__ __forceinline__ float box_area(const float4 b) {
    return __fmul_rn(__fsub_rn(b.z, b.x), __fsub_rn(b.w, b.y));
}

__device__ __forceinline__ void iou_iu(const float4 g, float areag,
                                       const float4 a, float areaa,
                                       float& inter, float& uni) {
    const float ix0 = fmaxf(g.x, a.x);
    const float iy0 = fmaxf(g.y, a.y);
    const float ix1 = fminf(g.z, a.z);
    const float iy1 = fminf(g.w, a.w);
    const float ww  = fmaxf(__fsub_rn(ix1, ix0), 0.0f);
    const float hh  = fmaxf(__fsub_rn(iy1, iy0), 0.0f);
    inter = __fmul_rn(ww, hh);
    uni   = __fsub_rn(__fadd_rn(areag, areaa), inter);
}

// ---------------------------------------------------------------------------
// Kernel 1: highest_per_gt[b][g]. Lane = gt, warps stride anchors staged in
// SMEM (broadcast LDS.128). Branch-free cross-multiplication running max of
// the exact ratio; ONE __fdiv_rn per lane at the end. fl is monotone, so
// fl(max exact ratio) == max of rounded quotients == reference value, and
// atomicMax over per-chunk fl-maxes composes correctly.
// ---------------------------------------------------------------------------
#define K1_CHUNK 2048

__global__ __launch_bounds__(256) void k_gtmax(
    const float4* __restrict__ anchors,
    const float4* __restrict__ gt,
    int A)
{
    __shared__ float4 sanch[K1_CHUNK];
    const int b    = blockIdx.y;
    const int lane = threadIdx.x & 31;
    const int warp = threadIdx.x >> 5;

    const float4 g4   = gt[b * 32 + lane];
    const float areag = box_area(g4);

    const int base  = blockIdx.x * K1_CHUNK;
    const int count = min(K1_CHUNK, A - base);

    for (int i = threadIdx.x; i < count; i += 256)
        sanch[i] = anchors[base + i];
    __syncthreads();

    float bi = 0.0f, bu = 1.0f;
#pragma unroll 4
    for (int j = warp; j < count; j += 8) {
        const float4 a4   = sanch[j];                // warp-broadcast
        const float areaa = box_area(a4);
        float inter, uni;
        iou_iu(g4, areag, a4, areaa, inter, uni);
        const float p1 = __fmul_rn(inter, bu);
        const float p2 = __fmul_rn(bi, uni);
        const bool upd = p1 > p2;                    // zeros never win (p1==0)
        bi = upd ? inter : bi;
        bu = upd ? uni   : bu;
    }
    const float h = __fdiv_rn(bi, bu);               // bi=0 -> 0/1 = 0 exact
    atomicMax(&g_highest[b * 32 + lane], __float_as_uint(h));
}

// ---------------------------------------------------------------------------
// Kernel 2: per (image, anchor) labeling + matched box + centerness.
// Branch-free cross-mult max/argmax (strict > keeps first index == reference
// tie-break); lq equality check only inside a 1e-6 band around the gt's
// global max (~1 anchor per gt -> branch essentially never taken per warp).
// ---------------------------------------------------------------------------
__global__ __launch_bounds__(256) void k_label(
    const float4* __restrict__ anchors,
    const float4* __restrict__ gt,
    float* __restrict__ out,
    int A, int B)
{
    __shared__ float4 sgt[32];     // gt box
    __shared__ float4 saux[32];    // {area_g, h, h*0.999999, unused}
    __shared__ int s_anyz;         // any gt with h == 0 -> lq true for ALL anchors

    const int b = blockIdx.y;
    if (threadIdx.x < 32) {
        const float4 g4 = gt[b * 32 + threadIdx.x];
        sgt[threadIdx.x] = g4;
        const float h = __uint_as_float(g_highest[b * 32 + threadIdx.x]);
        saux[threadIdx.x] = make_float4(box_area(g4), h,
                                        __fmul_rn(h, 0.999999f), 0.0f);
        const unsigned zb = __ballot_sync(0xffffffffu, h == 0.0f);
        if (threadIdx.x == 0) s_anyz = (zb != 0u);
    }
    __syncthreads();

    const int a = blockIdx.x * 256 + threadIdx.x;
    if (a >= A) return;

    const float4 a4   = anchors[a];
    const float areaa = box_area(a4);

    float bi = 0.0f, bu = 1.0f;   // running exact-ratio max as (inter, union)
    int   bidx = 0;
    bool  lq   = (s_anyz != 0);   // h_g==0 => iou 0 == h for every anchor

#pragma unroll
    for (int g = 0; g < 32; g++) {
        const float4 g4  = sgt[g];
        const float4 aux = saux[g];
        float inter, uni;
        iou_iu(g4, aux.x, a4, areaa, inter, uni);

        const float p1 = __fmul_rn(inter, bu);
        const float p2 = __fmul_rn(bi, uni);
        const bool upd = p1 > p2;
        bi   = upd ? inter : bi;
        bu   = upd ? uni   : bu;
        bidx = upd ? g     : bidx;

        // lq band: fl(inter/uni)==h possible only when inter >= uni*h*(1-1e-6).
        // h is the GLOBAL max for gt g -> ~1 hit per gt over 200k anchors.
        if (inter >= __fmul_rn(uni, aux.z) && aux.z > 0.0f) {
            lq = lq || (__fdiv_rn(inter, uni) == aux.y);
        }
    }

    const float val = __fdiv_rn(bi, bu);     // exact rounded max (monotonicity)
    const int gl = (lq || val >= 0.7f) ? 1 : ((val >= 0.3f) ? -1 : 0);
    const int ol = (lq || val >= 0.3f) ? 1 : ((val >= 0.1f) ? -1 : 0);

    const float4 tb4 = sgt[bidx];            // matched gt box (shared argmax)

    // deltas permuted [0,2,1,3]: [(cx-x0)/w, (x1-cx)/w, (cy-y0)/h, (y1-cy)/h]
    const float cx = 0.5f * (a4.x + a4.z);
    const float cy = 0.5f * (a4.y + a4.w);
    const float w  = a4.z - a4.x;
    const float hg = a4.w - a4.y;
    const float nl = cx - tb4.x;
    const float nr = tb4.z - cx;
    const float nt = cy - tb4.y;
    const float nb = tb4.w - cy;

    float cent = 0.0f;
    // sign(n/w) == sign(n) since w,h > 0: in-box test on numerators is exact
    if (ol != 0 && nl >= 0.0f && nr >= 0.0f && nt >= 0.0f && nb >= 0.0f) {
        // min(l,r)/(max(l,r)+eps) == min(nl,nr)/(max(nl,nr)+eps*w) (w>0)
        const float rx = __fdividef(fminf(nl, nr),
                                    __fmaf_rn(1e-12f, w,  fmaxf(nl, nr)));
        const float ry = __fdividef(fminf(nt, nb),
                                    __fmaf_rn(1e-12f, hg, fmaxf(nt, nb)));
        const float prod = rx * ry;
        cent = (prod > 0.0f) ? sqrtf(prod) : 0.0f;
    }

    // layout: [gt_labels B*A][matched B*A*4][obj_labels B*A][centerness B*A]
    const size_t BA = (size_t)B * (size_t)A;
    const size_t o  = (size_t)b * (size_t)A + (size_t)a;

    out[o] = (float)gl;
    reinterpret_cast<float4*>(out + BA)[o] = tb4;
    out[BA * 5 + o] = (float)ol;
    out[BA * 6 + o] = cent;
}

extern "C" void kernel_launch(void* const* d_in, const int* in_sizes, int n_in,
                              void* d_out, int out_size)
{
    const float4* gt      = (const float4*)d_in[0];   // [B,32,4] f32
    const float4* anchors = (const float4*)d_in[1];   // [A,4]    f32
    const int B = in_sizes[0] / (32 * 4);
    const int A = in_sizes[1] / 4;
    float* out = (float*)d_out;

    k_init_highest<<<1, 1024>>>();

    dim3 g1((A + K1_CHUNK - 1) / K1_CHUNK, B);
    k_gtmax<<<g1, 256>>>(anchors, gt, A);

    dim3 g2((A + 255) / 256, B);
    k_label<<<g2, 256>>>(anchors, gt, out, A, B);
}

// round 4
// speedup vs baseline: 1.4191x; 1.1541x over previous
#include <cuda_runtime.h>
#include <math.h>

// Per-(image,gt) max IoU (rounded quotient, reference semantics via rounding
// monotonicity), stored as float bits in uint (IoU >= 0 -> uint max == float max).
__device__ unsigned int g_highest[256];

// Deterministic round-to-nearest helpers (fast-math immune) so every value
// feeding the lq equality test is bit-identical across kernels.
__device__ __forceinline__ float box_area(const float4 b) {
    return __fmul_rn(__fsub_rn(b.z, b.x), __fsub_rn(b.w, b.y));
}

// inter = clip(min(g.hi,a.hi)-max(g.lo,a.lo),0) product — exact ref sequence.
__device__ __forceinline__ float inter_of(const float4 g, const float4 a) {
    const float ww = fmaxf(__fsub_rn(fminf(g.z, a.z), fmaxf(g.x, a.x)), 0.0f);
    const float hh = fmaxf(__fsub_rn(fminf(g.w, a.w), fmaxf(g.y, a.y)), 0.0f);
    return __fmul_rn(ww, hh);
}

// ---------------------------------------------------------------------------
// Kernel 1: highest_per_gt[b][g]. Lane = gt, 8 warps stride anchors staged in
// SMEM (broadcast LDS). Branch-free running max of the exact ratio inter/S
// (S = area_g + area_a; iou = r/(1-r) with r = inter/S is monotone in r, so
// the argmax matches iou's). One __fdiv_rn per lane at the end; fl monotone
// => result equals max of rounded quotients (reference). Block-level max
// reduction before atomicMax (32 atomics/block instead of 256).
// ---------------------------------------------------------------------------
#define K1_CHUNK 2048

__global__ __launch_bounds__(256) void k_gtmax(
    const float4* __restrict__ anchors,
    const float4* __restrict__ gt,
    int A)
{
    __shared__ float4 sanch[K1_CHUNK];
    __shared__ float  sarea[K1_CHUNK];
    __shared__ float  sred[8][32];

    const int b    = blockIdx.y;
    const int lane = threadIdx.x & 31;
    const int warp = threadIdx.x >> 5;

    const float4 g4   = gt[b * 32 + lane];
    const float areag = box_area(g4);

    const int base  = blockIdx.x * K1_CHUNK;
    const int count = min(K1_CHUNK, A - base);

    for (int i = threadIdx.x; i < count; i += 256) {
        const float4 a4 = anchors[base + i];
        sanch[i] = a4;
        sarea[i] = box_area(a4);
    }
    __syncthreads();

    float bi = 0.0f, bS = 1.0f;
#pragma unroll 4
    for (int j = warp; j < count; j += 8) {
        const float4 a4 = sanch[j];                       // warp-broadcast
        const float S   = __fadd_rn(areag, sarea[j]);
        const float inter = inter_of(g4, a4);
        const bool upd = __fmul_rn(inter, bS) > __fmul_rn(bi, S);
        bi = upd ? inter : bi;
        bS = upd ? S     : bS;
    }
    // winner's union recomputed bit-exactly: uni = fl(S - inter)
    sred[warp][lane] = __fdiv_rn(bi, __fsub_rn(bS, bi));  // bi=0 -> 0/1 = 0
    __syncthreads();

    if (warp == 0) {
        float m = sred[0][lane];
#pragma unroll
        for (int w = 1; w < 8; w++) m = fmaxf(m, sred[w][lane]);
        atomicMax(&g_highest[b * 32 + lane], __float_as_uint(m));
    }
}

// ---------------------------------------------------------------------------
// Kernel 2: per (image, anchor) labeling + matched box + centerness.
// Branch-free inner loop: cross-mult max/argmax on (inter, S) and a float
// band accumulator band = max(band, inter - S*h') where h' = h*d/(1+h*d)*d
// (d = 0.99999): fl(inter/uni)==h implies inter/S >= h' with slack ~1e-5 >>
// fp32 rounding, so no true lq anchor is missed. Divisions happen only in a
// post-loop rescan taken by ~0.13% of threads.
// ---------------------------------------------------------------------------
__global__ __launch_bounds__(256) void k_label(
    const float4* __restrict__ anchors,
    const float4* __restrict__ gt,
    float* __restrict__ out,
    int A, int B)
{
    __shared__ float4 sgt[32];    // gt box
    __shared__ float2 sax[32];    // {area_g, h'}
    __shared__ float  s_h[32];    // exact global max per gt
    __shared__ int    s_anyz;     // any gt with h == 0 -> lq true for ALL anchors

    const int b = blockIdx.y;
    if (threadIdx.x < 32) {
        const float4 g4 = gt[b * 32 + threadIdx.x];
        sgt[threadIdx.x] = g4;
        const float h = __uint_as_float(g_highest[b * 32 + threadIdx.x]);
        s_h[threadIdx.x] = h;
        float hp;
        if (h > 0.0f) {
            const float hl = h * 0.99999f;
            hp = (hl / (1.0f + hl)) * 0.99999f;
        } else {
            hp = __int_as_float(0x7f800000);   // +inf: band never fires
        }
        sax[threadIdx.x] = make_float2(box_area(g4), hp);
        const unsigned zb = __ballot_sync(0xffffffffu, h == 0.0f);
        if (threadIdx.x == 0) s_anyz = (zb != 0u);
    }
    __syncthreads();

    const int a = blockIdx.x * 256 + threadIdx.x;
    if (a >= A) return;

    const float4 a4   = anchors[a];
    const float areaa = box_area(a4);

    float bi = 0.0f, bS = 1.0f;   // running exact-ratio max as (inter, S)
    int   bidx = 0;
    float band = -1.0f;           // >= 0 iff some gt may satisfy iou == h

#pragma unroll
    for (int g = 0; g < 32; g++) {
        const float4 g4 = sgt[g];
        const float2 ax = sax[g];
        const float S     = __fadd_rn(ax.x, areaa);
        const float inter = inter_of(g4, a4);

        const bool upd = __fmul_rn(inter, bS) > __fmul_rn(bi, S);
        bi   = upd ? inter : bi;
        bS   = upd ? S     : bS;
        bidx = upd ? g     : bidx;

        band = fmaxf(band, __fmaf_rn(S, -ax.y, inter));
    }

    bool lq = (s_anyz != 0);
    if (band >= 0.0f) {           // rare (~0.13% of threads, ~4% of warps)
#pragma unroll 4
        for (int g = 0; g < 32; g++) {
            const float4 g4 = sgt[g];
            const float S     = __fadd_rn(sax[g].x, areaa);
            const float inter = inter_of(g4, a4);
            const float uni   = __fsub_rn(S, inter);
            lq = lq || (__fdiv_rn(inter, uni) == s_h[g]);
        }
    }

    const float val = __fdiv_rn(bi, __fsub_rn(bS, bi));  // exact rounded max
    const int gl = (lq || val >= 0.7f) ? 1 : ((val >= 0.3f) ? -1 : 0);
    const int ol = (lq || val >= 0.3f) ? 1 : ((val >= 0.1f) ? -1 : 0);

    const float4 tb4 = sgt[bidx];            // matched gt box (shared argmax)

    // deltas permuted [0,2,1,3]: [(cx-x0)/w, (x1-cx)/w, (cy-y0)/h, (y1-cy)/h]
    const float cx = 0.5f * (a4.x + a4.z);
    const float cy = 0.5f * (a4.y + a4.w);
    const float w  = a4.z - a4.x;
    const float hg = a4.w - a4.y;
    const float nl = cx - tb4.x;
    const float nr = tb4.z - cx;
    const float nt = cy - tb4.y;
    const float nb = tb4.w - cy;

    float cent = 0.0f;
    // sign(n/w) == sign(n) since w,h > 0: in-box test on numerators is exact
    if (ol != 0 && nl >= 0.0f && nr >= 0.0f && nt >= 0.0f && nb >= 0.0f) {
        // min(l,r)/(max(l,r)+eps) == min(nl,nr)/(max(nl,nr)+eps*w)  (w > 0)
        const float rx = __fdividef(fminf(nl, nr),
                                    __fmaf_rn(1e-12f, w,  fmaxf(nl, nr)));
        const float ry = __fdividef(fminf(nt, nb),
                                    __fmaf_rn(1e-12f, hg, fmaxf(nt, nb)));
        const float prod = rx * ry;
        cent = (prod > 0.0f) ? sqrtf(prod) : 0.0f;
    }

    // layout: [gt_labels B*A][matched B*A*4][obj_labels B*A][centerness B*A]
    const size_t BA = (size_t)B * (size_t)A;
    const size_t o  = (size_t)b * (size_t)A + (size_t)a;

    out[o] = (float)gl;
    reinterpret_cast<float4*>(out + BA)[o] = tb4;
    out[BA * 5 + o] = (float)ol;
    out[BA * 6 + o] = cent;
}

extern "C" void kernel_launch(void* const* d_in, const int* in_sizes, int n_in,
                              void* d_out, int out_size)
{
    const float4* gt      = (const float4*)d_in[0];   // [B,32,4] f32
    const float4* anchors = (const float4*)d_in[1];   // [A,4]    f32
    const int B = in_sizes[0] / (32 * 4);
    const int A = in_sizes[1] / 4;
    float* out = (float*)d_out;

    // reset g_highest via a graph memset node (cheaper than a kernel)
    void* hp = nullptr;
    cudaGetSymbolAddress(&hp, g_highest);
    cudaMemsetAsync(hp, 0, 256 * sizeof(unsigned int), 0);

    dim3 g1((A + K1_CHUNK - 1) / K1_CHUNK, B);
    k_gtmax<<<g1, 256>>>(anchors, gt, A);

    dim3 g2((A + 255) / 256, B);
    k_label<<<g2, 256>>>(anchors, gt, out, A, B);
}